// round 9
// baseline (speedup 1.0000x reference)
#include <cuda_runtime.h>
#include <math.h>

#define BB   32
#define CC   256
#define C8   32
#define NPIX 1024
#define NROWS 320   // 32 q + 32 k + 256 v rows stacked

// ---- scratch (device globals; allocation-free per harness rules) ----
__device__ float g_q[(size_t)BB * C8 * NPIX];        // [b][d][m]  4 MB
__device__ float g_k[(size_t)BB * C8 * NPIX];        // [b][d][n]  4 MB
__device__ float g_v[(size_t)BB * CC * NPIX];        // [b][c][n] 32 MB
__device__ float g_attn[(size_t)BB * NPIX * NPIX];   // [b][m][n] unnormalized exp(E), 128 MB
__device__ float g_inv[(size_t)BB * NPIX];           // 1/rowsum, 128 KB

// ============================================================================
// tf32 mma helpers (fragment mappings verified in round 4):
//  A frag (M=16, K=8), value (m,k): lane=(m&7)*4+(k&3),
//      e = ((k>>2)&1) + 2*((m>>3)&1); stored uint4/lane; consumed (x,z,y,w).
//  B frag (N=8, K=8), value (n,k): lane=(n&7)*4+(k&3), e=(k>>2)&1; uint2/lane.
//  D frag: row=(lane>>2)(+8), col=2*(lane&3)(+1): .x .y / .z .w
// ============================================================================
__device__ __forceinline__ unsigned int f2tf32(float f) {
    unsigned int r;
    asm("cvt.rna.tf32.f32 %0, %1;" : "=r"(r) : "f"(f));
    return r;
}

__device__ __forceinline__ void mma_tf32(float4& d,
    unsigned int a0, unsigned int a1, unsigned int a2, unsigned int a3,
    unsigned int b0, unsigned int b1)
{
    asm volatile(
        "mma.sync.aligned.m16n8k8.row.col.f32.tf32.tf32.f32 "
        "{%0,%1,%2,%3}, {%4,%5,%6,%7}, {%8,%9}, {%0,%1,%2,%3};"
        : "+f"(d.x), "+f"(d.y), "+f"(d.z), "+f"(d.w)
        : "r"(a0), "r"(a1), "r"(a2), "r"(a3), "r"(b0), "r"(b1));
}

// smem offsets (uint index) for fragment-ordered tiles
__device__ __forceinline__ int offA(int m, int k) {   // tile M x 32k, frag order
    return ((m >> 4) * 4 + (k >> 3)) * 128 + ((m & 7) * 4 + (k & 3)) * 4
         + ((k >> 2) & 1) + 2 * ((m >> 3) & 1);
}
__device__ __forceinline__ int offB(int n, int k) {   // tile N x 32k, frag order
    return ((n >> 3) * 4 + (k >> 3)) * 64 + ((n & 7) * 4 + (k & 3)) * 2
         + ((k >> 2) & 1);
}

// ============================================================================
// Kernel 1 (tf32 TC): fused q/k/v projection.
// P[320,1024] = W[320,256] @ X[256,1024] + bias, per batch.
// Block tile 64(r) x 128(n), K-chunks of 32. 8 warps = 2(M) x 4(N).
// ============================================================================
__device__ __forceinline__ void proj_store(int b, int r, int n, float v0, float v1,
    const float* __restrict__ bq, const float* __restrict__ bk,
    const float* __restrict__ bv)
{
    float bias; float* dst;
    if (r < 32)      { bias = bq[r];      dst = &g_q[((size_t)b * C8 + r) * NPIX]; }
    else if (r < 64) { bias = bk[r - 32]; dst = &g_k[((size_t)b * C8 + (r - 32)) * NPIX]; }
    else             { bias = bv[r - 64]; dst = &g_v[((size_t)b * CC + (r - 64)) * NPIX]; }
    float2 o; o.x = v0 + bias; o.y = v1 + bias;
    *(float2*)&dst[n] = o;
}

__global__ __launch_bounds__(256) void proj_kernel(
    const float* __restrict__ x,
    const float* __restrict__ Wq, const float* __restrict__ bq,
    const float* __restrict__ Wk, const float* __restrict__ bk,
    const float* __restrict__ Wv, const float* __restrict__ bv)
{
    const int b  = blockIdx.x;
    const int r0 = blockIdx.y * 64;    // 5 r-tiles
    const int n0 = blockIdx.z * 128;   // 8 n-tiles

    __shared__ unsigned int sA[2048];  // W tile 64x32, frag order (8 KB)
    __shared__ unsigned int sB[4096];  // X tile 128x32, frag order (16 KB)

    const int t    = threadIdx.x;
    const int lane = t & 31;
    const int w    = t >> 5;
    const int wm   = w & 1;    // M half (32 rows)
    const int wn   = w >> 1;   // N quarter (32 cols)

    float4 acc[2][4];
    #pragma unroll
    for (int f = 0; f < 2; f++)
        #pragma unroll
        for (int g = 0; g < 4; g++) acc[f][g] = make_float4(0.f, 0.f, 0.f, 0.f);

    for (int c0 = 0; c0 < CC; c0 += 32) {
        #pragma unroll
        for (int i = 0; i < 8; i++) {       // stage W (64x32)
            int idx = t + i * 256;
            int r = idx >> 5, k = idx & 31;
            int rg = r0 + r;
            float wv;
            if (rg < 32)      wv = Wq[rg * CC + c0 + k];
            else if (rg < 64) wv = Wk[(rg - 32) * CC + c0 + k];
            else              wv = Wv[(rg - 64) * CC + c0 + k];
            sA[offA(r, k)] = f2tf32(wv);
        }
        #pragma unroll
        for (int i = 0; i < 16; i++) {      // stage X (128x32)
            int idx = t + i * 256;
            int n = idx & 127, k = idx >> 7;
            sB[offB(n, k)] = f2tf32(x[((size_t)b * CC + c0 + k) * NPIX + n0 + n]);
        }
        __syncthreads();

        #pragma unroll
        for (int j = 0; j < 4; j++) {
            uint4 av[2];
            #pragma unroll
            for (int f = 0; f < 2; f++)
                av[f] = ((const uint4*)sA)[((wm * 2 + f) * 4 + j) * 32 + lane];
            uint2 bv2[4];
            #pragma unroll
            for (int g = 0; g < 4; g++)
                bv2[g] = ((const uint2*)sB)[((wn * 4 + g) * 4 + j) * 32 + lane];
            #pragma unroll
            for (int f = 0; f < 2; f++)
                #pragma unroll
                for (int g = 0; g < 4; g++)
                    mma_tf32(acc[f][g], av[f].x, av[f].z, av[f].y, av[f].w,
                             bv2[g].x, bv2[g].y);
        }
        __syncthreads();
    }

    const int rb = r0 + wm * 32 + (lane >> 2);
    const int nb = n0 + wn * 32 + 2 * (lane & 3);
    #pragma unroll
    for (int f = 0; f < 2; f++) {
        #pragma unroll
        for (int g = 0; g < 4; g++) {
            int r = rb + f * 16;
            int n = nb + g * 8;
            proj_store(b, r,     n, acc[f][g].x, acc[f][g].y, bq, bk, bv);
            proj_store(b, r + 8, n, acc[f][g].z, acc[f][g].w, bq, bk, bv);
        }
    }
}

// ============================================================================
// Kernel 2 (tf32 TC): fused energy + exp + row-sum.
// Per block: 64 m-rows, full n=1024 in chunks of 128.
// E[m][n] = sum_d q[b][d][m] k[b][d][n]; writes exp(E) to g_attn (unnormalized),
// accumulates per-row sums; stores 1/sum to g_inv. No max-subtract (|E|<~35).
// ============================================================================
__global__ __launch_bounds__(256) void energy_exp_kernel()
{
    const int b  = blockIdx.x;
    const int m0 = blockIdx.y * 64;    // 16 m-tiles

    __shared__ unsigned int sQ[2048];  // Q tile 64m x 32d, frag order
    __shared__ unsigned int sK[4096];  // K tile 128n x 32d, frag order
    __shared__ float rowsum[64];

    const int t    = threadIdx.x;
    const int lane = t & 31;
    const int w    = t >> 5;
    const int wm   = w & 1;
    const int wn   = w >> 1;

    // stage Q once (reused across all n-chunks)
    #pragma unroll
    for (int i = 0; i < 8; i++) {
        int idx = t + i * 256;
        int m = idx & 63, d = idx >> 6;
        sQ[offA(m, d)] = f2tf32(g_q[((size_t)b * C8 + d) * NPIX + m0 + m]);
    }
    if (t < 64) rowsum[t] = 0.0f;
    __syncthreads();

    for (int n0 = 0; n0 < NPIX; n0 += 128) {
        #pragma unroll
        for (int i = 0; i < 16; i++) {
            int idx = t + i * 256;
            int n = idx & 127, d = idx >> 7;
            sK[offB(n, d)] = f2tf32(g_k[((size_t)b * C8 + d) * NPIX + n0 + n]);
        }
        __syncthreads();

        float4 acc[2][4];
        #pragma unroll
        for (int f = 0; f < 2; f++)
            #pragma unroll
            for (int g = 0; g < 4; g++) acc[f][g] = make_float4(0.f, 0.f, 0.f, 0.f);

        #pragma unroll
        for (int j = 0; j < 4; j++) {
            uint4 av[2];
            #pragma unroll
            for (int f = 0; f < 2; f++)
                av[f] = ((const uint4*)sQ)[((wm * 2 + f) * 4 + j) * 32 + lane];
            uint2 bv2[4];
            #pragma unroll
            for (int g = 0; g < 4; g++)
                bv2[g] = ((const uint2*)sK)[((wn * 4 + g) * 4 + j) * 32 + lane];
            #pragma unroll
            for (int f = 0; f < 2; f++)
                #pragma unroll
                for (int g = 0; g < 4; g++)
                    mma_tf32(acc[f][g], av[f].x, av[f].z, av[f].y, av[f].w,
                             bv2[g].x, bv2[g].y);
        }

        // exp, write unnormalized attn, accumulate row sums
        #pragma unroll
        for (int f = 0; f < 2; f++) {
            float slo = 0.0f, shi = 0.0f;
            const int m_lo = m0 + wm * 32 + f * 16 + (lane >> 2);
            #pragma unroll
            for (int g = 0; g < 4; g++) {
                float e0 = __expf(acc[f][g].x);
                float e1 = __expf(acc[f][g].y);
                float e2 = __expf(acc[f][g].z);
                float e3 = __expf(acc[f][g].w);
                int n = n0 + wn * 32 + g * 8 + 2 * (lane & 3);
                size_t a0 = ((size_t)b * NPIX + m_lo) * NPIX + n;
                float2 lo; lo.x = e0; lo.y = e1;
                float2 hi; hi.x = e2; hi.y = e3;
                *(float2*)&g_attn[a0] = lo;
                *(float2*)&g_attn[a0 + (size_t)8 * NPIX] = hi;
                slo += e0 + e1;
                shi += e2 + e3;
            }
            slo += __shfl_xor_sync(0xffffffffu, slo, 1);
            slo += __shfl_xor_sync(0xffffffffu, slo, 2);
            shi += __shfl_xor_sync(0xffffffffu, shi, 1);
            shi += __shfl_xor_sync(0xffffffffu, shi, 2);
            if ((lane & 3) == 0) {
                atomicAdd(&rowsum[wm * 32 + f * 16 + (lane >> 2)], slo);
                atomicAdd(&rowsum[wm * 32 + f * 16 + (lane >> 2) + 8], shi);
            }
        }
        __syncthreads();
    }

    if (t < 64)
        g_inv[(size_t)b * NPIX + m0 + t] = 1.0f / rowsum[t];
}

// ============================================================================
// Kernel 3 (tf32 TC): out[b][c][m] = gamma * inv_s[m] * sum_n V[c][n]*expE[m][n] + x
// Block tile 128(c) x 128(m), K-chunk 32. Raw fp32 bits fed as tf32 (truncate).
// ============================================================================
__global__ __launch_bounds__(256, 2) void out_kernel(
    const float* __restrict__ x, const float* __restrict__ gamma,
    float* __restrict__ out)
{
    const int b  = blockIdx.x;
    const int c0 = blockIdx.y * 128;   // 2 c-tiles
    const int m0 = blockIdx.z * 128;   // 8 m-tiles

    __shared__ unsigned int sV[4096];  // V frag tile (16 KB)
    __shared__ unsigned int sB[4096];  // attn frag tile (16 KB)

    const int t    = threadIdx.x;
    const int lane = t & 31;
    const int w    = t >> 5;
    const int wc   = w & 1;
    const int wm   = w >> 1;

    const int srow = t >> 5;
    const int snn  = t & 31;
    const int sj   = snn >> 3;
    const int su   = (snn >> 2) & 1;
    const int slaneSlot = srow * 4 + (snn & 3);
    const int baseA = sj * 128 + slaneSlot * 4 + su;
    const int baseB = sj * 64  + slaneSlot * 2 + su;

    const float* vsrc = g_v    + ((size_t)b * CC   + c0 + srow) * NPIX + snn;
    const float* asrc = g_attn + ((size_t)b * NPIX + m0 + srow) * NPIX + snn;

    float4 acc[4][4];
    #pragma unroll
    for (int f = 0; f < 4; f++)
        #pragma unroll
        for (int g = 0; g < 4; g++) acc[f][g] = make_float4(0.f, 0.f, 0.f, 0.f);

    for (int n0 = 0; n0 < NPIX; n0 += 32) {
        #pragma unroll
        for (int i = 0; i < 16; i++) {
            const int cA = (((i >> 3) * 4 + ((i >> 1) & 3)) * 4) * 128 + 2 * (i & 1);
            sV[baseA + cA] = __float_as_uint(vsrc[(size_t)(8 * i) * NPIX + n0]);
        }
        #pragma unroll
        for (int i = 0; i < 16; i++) {
            sB[i * 256 + baseB] = __float_as_uint(asrc[(size_t)(8 * i) * NPIX + n0]);
        }
        __syncthreads();

        #pragma unroll
        for (int j = 0; j < 4; j++) {
            uint4 av[4];
            #pragma unroll
            for (int f = 0; f < 4; f++)
                av[f] = ((const uint4*)sV)[((wc * 4 + f) * 4 + j) * 32 + lane];
            uint2 bv2[4];
            #pragma unroll
            for (int g = 0; g < 4; g++)
                bv2[g] = ((const uint2*)sB)[((wm * 4 + g) * 4 + j) * 32 + lane];

            #pragma unroll
            for (int f = 0; f < 4; f++)
                #pragma unroll
                for (int g = 0; g < 4; g++)
                    mma_tf32(acc[f][g], av[f].x, av[f].z, av[f].y, av[f].w,
                             bv2[g].x, bv2[g].y);
        }
        __syncthreads();
    }

    // epilogue: out = gamma * inv_s[m] * acc + x
    const float gm = *gamma;
    const int cbase = c0 + wc * 64 + (lane >> 2);
    const int mbase = m0 + wm * 32 + 2 * (lane & 3);

    #pragma unroll
    for (int f = 0; f < 4; f++) {
        #pragma unroll
        for (int g = 0; g < 4; g++) {
            const int c = cbase + f * 16;
            const int m = mbase + g * 8;
            float2 inv2 = *(const float2*)&g_inv[(size_t)b * NPIX + m];
            const float s0 = gm * inv2.x;
            const float s1 = gm * inv2.y;
            size_t a0i = ((size_t)b * CC + c) * NPIX + m;
            size_t a1i = a0i + (size_t)8 * NPIX;
            float2 x0 = *(const float2*)&x[a0i];
            float2 x1 = *(const float2*)&x[a1i];
            float2 o0, o1;
            o0.x = s0 * acc[f][g].x + x0.x;
            o0.y = s1 * acc[f][g].y + x0.y;
            o1.x = s0 * acc[f][g].z + x1.x;
            o1.y = s1 * acc[f][g].w + x1.y;
            *(float2*)&out[a0i] = o0;
            *(float2*)&out[a1i] = o1;
        }
    }
}

// ============================================================================
extern "C" void kernel_launch(void* const* d_in, const int* in_sizes, int n_in,
                              void* d_out, int out_size)
{
    (void)in_sizes; (void)n_in; (void)out_size;
    const float* x     = (const float*)d_in[0];
    const float* Wq    = (const float*)d_in[1];
    const float* bq    = (const float*)d_in[2];
    const float* Wk    = (const float*)d_in[3];
    const float* bk    = (const float*)d_in[4];
    const float* Wv    = (const float*)d_in[5];
    const float* bv    = (const float*)d_in[6];
    const float* gamma = (const float*)d_in[7];
    float* out = (float*)d_out;

    dim3 g1(BB, NROWS / 64, NPIX / 128);   // 32 x 5 x 8
    proj_kernel<<<g1, 256>>>(x, Wq, bq, Wk, bk, Wv, bv);

    dim3 g2(BB, NPIX / 64);                // 32 x 16
    energy_exp_kernel<<<g2, 256>>>();

    dim3 g4(BB, CC / 128, NPIX / 128);     // 32 x 2 x 8
    out_kernel<<<g4, 256>>>(x, gamma, out);
}

// round 12
// speedup vs baseline: 1.0150x; 1.0150x over previous
#include <cuda_runtime.h>
#include <math.h>

#define BB   32
#define CC   256
#define C8   32
#define NPIX 1024
#define NROWS 320   // 32 q + 32 k + 256 v rows stacked

// ---- scratch (device globals; allocation-free per harness rules) ----
__device__ float g_q[(size_t)BB * C8 * NPIX];        // [b][d][m]  4 MB
__device__ float g_k[(size_t)BB * C8 * NPIX];        // [b][d][n]  4 MB
__device__ float g_v[(size_t)BB * CC * NPIX];        // [b][c][n] 32 MB
__device__ float g_attn[(size_t)BB * NPIX * NPIX];   // [b][m][n] unnormalized exp(E), 128 MB
__device__ float g_inv[(size_t)BB * NPIX];           // 1/rowsum, 128 KB

// ============================================================================
// tf32 mma helpers (fragment mappings verified in rounds 4/5):
//  A frag (16m x 8k) slot: lane=(m&7)*4+(k&3); uint4 elems =
//      e0=(m_lo,k_lo) e1=(m_lo,k_hi) e2=(m_hi,k_lo) e3=(m_hi,k_hi),
//      consumed by mma as (x,z,y,w).
//  B frag (8n x 8k) slot: lane=(n&7)*4+(k&3); uint2 = (k_lo, k_hi).
//  D frag: row=(lane>>2)(+8), col=2*(lane&3)(+1): .x .y / .z .w
// Staging is slot-per-thread: each thread gathers its slot's elements from
// gmem and does ONE lane-linear STS.128/STS.64 -> zero bank conflicts.
// ============================================================================
__device__ __forceinline__ unsigned int f2tf32(float f) {
    unsigned int r;
    asm("cvt.rna.tf32.f32 %0, %1;" : "=r"(r) : "f"(f));
    return r;
}

__device__ __forceinline__ void mma_tf32(float4& d,
    unsigned int a0, unsigned int a1, unsigned int a2, unsigned int a3,
    unsigned int b0, unsigned int b1)
{
    asm volatile(
        "mma.sync.aligned.m16n8k8.row.col.f32.tf32.tf32.f32 "
        "{%0,%1,%2,%3}, {%4,%5,%6,%7}, {%8,%9}, {%0,%1,%2,%3};"
        : "+f"(d.x), "+f"(d.y), "+f"(d.z), "+f"(d.w)
        : "r"(a0), "r"(a1), "r"(a2), "r"(a3), "r"(b0), "r"(b1));
}

// ============================================================================
// Kernel 1 (tf32 TC): fused q/k/v projection.
// P[320,1024] = W[320,256] @ X[256,1024] + bias, per batch.
// Block tile 64(r) x 128(n), K-chunks of 32. 8 warps = 2(M) x 4(N).
// ============================================================================
__device__ __forceinline__ float ldW(int r, int cidx,
    const float* __restrict__ Wq, const float* __restrict__ Wk,
    const float* __restrict__ Wv)
{
    if (r < 32)      return Wq[r * CC + cidx];
    else if (r < 64) return Wk[(r - 32) * CC + cidx];
    else             return Wv[(r - 64) * CC + cidx];
}

__device__ __forceinline__ void proj_store(int b, int r, int n, float v0, float v1,
    const float* __restrict__ bq, const float* __restrict__ bk,
    const float* __restrict__ bv)
{
    float bias; float* dst;
    if (r < 32)      { bias = bq[r];      dst = &g_q[((size_t)b * C8 + r) * NPIX]; }
    else if (r < 64) { bias = bk[r - 32]; dst = &g_k[((size_t)b * C8 + (r - 32)) * NPIX]; }
    else             { bias = bv[r - 64]; dst = &g_v[((size_t)b * CC + (r - 64)) * NPIX]; }
    float2 o; o.x = v0 + bias; o.y = v1 + bias;
    *(float2*)&dst[n] = o;
}

__global__ __launch_bounds__(256) void proj_kernel(
    const float* __restrict__ x,
    const float* __restrict__ Wq, const float* __restrict__ bq,
    const float* __restrict__ Wk, const float* __restrict__ bk,
    const float* __restrict__ Wv, const float* __restrict__ bv)
{
    const int b  = blockIdx.x;
    const int r0 = blockIdx.y * 64;    // 5 r-tiles
    const int n0 = blockIdx.z * 128;   // 8 n-tiles

    __shared__ unsigned int sA[2048];  // W tile 64x32: 16 A-regions x 32 x uint4
    __shared__ unsigned int sB[4096];  // X tile 128x32: 64 B-regions x 32 x uint2

    const int t    = threadIdx.x;
    const int lane = t & 31;
    const int w    = t >> 5;
    const int wm   = w & 1;    // M half (32 rows)
    const int wn   = w >> 1;   // N quarter (32 cols)

    // slot coords (region = (t>>5) + i*8)
    const int sml = lane >> 2;   // m/n local within 8
    const int skl = lane & 3;    // k local within 4

    float4 acc[2][4];
    #pragma unroll
    for (int f = 0; f < 2; f++)
        #pragma unroll
        for (int g = 0; g < 4; g++) acc[f][g] = make_float4(0.f, 0.f, 0.f, 0.f);

    for (int c0 = 0; c0 < CC; c0 += 32) {
        // ---- stage W (A-side): 16 regions, 2 slots/thread ----
        #pragma unroll
        for (int i = 0; i < 2; i++) {
            int region = (t >> 5) + i * 8;      // m16*4 + j
            int m16 = region >> 2, j = region & 3;
            int r = r0 + m16 * 16 + sml;
            int k = c0 + j * 8 + skl;
            uint4 s;
            s.x = f2tf32(ldW(r,     k,     Wq, Wk, Wv));
            s.y = f2tf32(ldW(r,     k + 4, Wq, Wk, Wv));
            s.z = f2tf32(ldW(r + 8, k,     Wq, Wk, Wv));
            s.w = f2tf32(ldW(r + 8, k + 4, Wq, Wk, Wv));
            ((uint4*)sA)[region * 32 + lane] = s;
        }
        // ---- stage X (B-side): 64 regions, 8 slots/thread ----
        #pragma unroll
        for (int i = 0; i < 8; i++) {
            int region = (t >> 5) + i * 8;      // n8*4 + j
            int n8 = region >> 2, j = region & 3;
            int n = n0 + n8 * 8 + sml;
            int k = c0 + j * 8 + skl;
            const float* src = &x[((size_t)b * CC + k) * NPIX + n];
            uint2 s;
            s.x = f2tf32(src[0]);
            s.y = f2tf32(src[4 * NPIX]);
            ((uint2*)sB)[region * 32 + lane] = s;
        }
        __syncthreads();

        #pragma unroll
        for (int j = 0; j < 4; j++) {
            uint4 av[2];
            #pragma unroll
            for (int f = 0; f < 2; f++)
                av[f] = ((const uint4*)sA)[((wm * 2 + f) * 4 + j) * 32 + lane];
            uint2 bv2[4];
            #pragma unroll
            for (int g = 0; g < 4; g++)
                bv2[g] = ((const uint2*)sB)[((wn * 4 + g) * 4 + j) * 32 + lane];
            #pragma unroll
            for (int f = 0; f < 2; f++)
                #pragma unroll
                for (int g = 0; g < 4; g++)
                    mma_tf32(acc[f][g], av[f].x, av[f].z, av[f].y, av[f].w,
                             bv2[g].x, bv2[g].y);
        }
        __syncthreads();
    }

    const int rb = r0 + wm * 32 + (lane >> 2);
    const int nb = n0 + wn * 32 + 2 * (lane & 3);
    #pragma unroll
    for (int f = 0; f < 2; f++) {
        #pragma unroll
        for (int g = 0; g < 4; g++) {
            int r = rb + f * 16;
            int n = nb + g * 8;
            proj_store(b, r,     n, acc[f][g].x, acc[f][g].y, bq, bk, bv);
            proj_store(b, r + 8, n, acc[f][g].z, acc[f][g].w, bq, bk, bv);
        }
    }
}

// ============================================================================
// Kernel 2 (tf32 TC): fused energy + exp + row-sum.
// Per block: 64 m-rows, full n=1024 in chunks of 128.
// Writes exp(E) to g_attn (unnormalized), 1/rowsum to g_inv.
// ============================================================================
__global__ __launch_bounds__(256) void energy_exp_kernel()
{
    const int b  = blockIdx.x;
    const int m0 = blockIdx.y * 64;    // 16 m-tiles

    __shared__ unsigned int sQ[2048];  // Q 64m x 32d: 16 A-regions
    __shared__ unsigned int sK[4096];  // K 128n x 32d: 64 B-regions
    __shared__ float rowsum[64];

    const int t    = threadIdx.x;
    const int lane = t & 31;
    const int w    = t >> 5;
    const int wm   = w & 1;
    const int wn   = w >> 1;

    const int sml = lane >> 2;
    const int skl = lane & 3;

    // stage Q once (reused across all n-chunks): 2 slots/thread
    #pragma unroll
    for (int i = 0; i < 2; i++) {
        int region = (t >> 5) + i * 8;
        int m16 = region >> 2, j = region & 3;
        int m = m0 + m16 * 16 + sml;
        int d = j * 8 + skl;
        const float* q0 = &g_q[((size_t)b * C8 + d) * NPIX + m];
        uint4 s;
        s.x = f2tf32(q0[0]);
        s.y = f2tf32(q0[4 * NPIX]);
        s.z = f2tf32(q0[8]);
        s.w = f2tf32(q0[4 * NPIX + 8]);
        ((uint4*)sQ)[region * 32 + lane] = s;
    }
    if (t < 64) rowsum[t] = 0.0f;
    __syncthreads();

    for (int n0 = 0; n0 < NPIX; n0 += 128) {
        #pragma unroll
        for (int i = 0; i < 8; i++) {
            int region = (t >> 5) + i * 8;
            int n8 = region >> 2, j = region & 3;
            int n = n0 + n8 * 8 + sml;
            int d = j * 8 + skl;
            const float* k0 = &g_k[((size_t)b * C8 + d) * NPIX + n];
            uint2 s;
            s.x = f2tf32(k0[0]);
            s.y = f2tf32(k0[4 * NPIX]);
            ((uint2*)sK)[region * 32 + lane] = s;
        }
        __syncthreads();

        float4 acc[2][4];
        #pragma unroll
        for (int f = 0; f < 2; f++)
            #pragma unroll
            for (int g = 0; g < 4; g++) acc[f][g] = make_float4(0.f, 0.f, 0.f, 0.f);

        #pragma unroll
        for (int j = 0; j < 4; j++) {
            uint4 av[2];
            #pragma unroll
            for (int f = 0; f < 2; f++)
                av[f] = ((const uint4*)sQ)[((wm * 2 + f) * 4 + j) * 32 + lane];
            uint2 bv2[4];
            #pragma unroll
            for (int g = 0; g < 4; g++)
                bv2[g] = ((const uint2*)sK)[((wn * 4 + g) * 4 + j) * 32 + lane];
            #pragma unroll
            for (int f = 0; f < 2; f++)
                #pragma unroll
                for (int g = 0; g < 4; g++)
                    mma_tf32(acc[f][g], av[f].x, av[f].z, av[f].y, av[f].w,
                             bv2[g].x, bv2[g].y);
        }

        // exp, write unnormalized attn, accumulate row sums
        #pragma unroll
        for (int f = 0; f < 2; f++) {
            float slo = 0.0f, shi = 0.0f;
            const int m_lo = m0 + wm * 32 + f * 16 + (lane >> 2);
            #pragma unroll
            for (int g = 0; g < 4; g++) {
                float e0 = __expf(acc[f][g].x);
                float e1 = __expf(acc[f][g].y);
                float e2 = __expf(acc[f][g].z);
                float e3 = __expf(acc[f][g].w);
                int n = n0 + wn * 32 + g * 8 + 2 * (lane & 3);
                size_t a0 = ((size_t)b * NPIX + m_lo) * NPIX + n;
                float2 lo; lo.x = e0; lo.y = e1;
                float2 hi; hi.x = e2; hi.y = e3;
                *(float2*)&g_attn[a0] = lo;
                *(float2*)&g_attn[a0 + (size_t)8 * NPIX] = hi;
                slo += e0 + e1;
                shi += e2 + e3;
            }
            slo += __shfl_xor_sync(0xffffffffu, slo, 1);
            slo += __shfl_xor_sync(0xffffffffu, slo, 2);
            shi += __shfl_xor_sync(0xffffffffu, shi, 1);
            shi += __shfl_xor_sync(0xffffffffu, shi, 2);
            if ((lane & 3) == 0) {
                atomicAdd(&rowsum[wm * 32 + f * 16 + (lane >> 2)], slo);
                atomicAdd(&rowsum[wm * 32 + f * 16 + (lane >> 2) + 8], shi);
            }
        }
        __syncthreads();
    }

    if (t < 64)
        g_inv[(size_t)b * NPIX + m0 + t] = 1.0f / rowsum[t];
}

// ============================================================================
// Kernel 3 (tf32 TC): out[b][c][m] = gamma * inv_s[m] * sum_n V[c][n]*expE[m][n] + x
// Block tile 128(c) x 128(m), K-chunk 32. Raw fp32 bits fed as tf32 (truncate).
// ============================================================================
__global__ __launch_bounds__(256, 2) void out_kernel(
    const float* __restrict__ x, const float* __restrict__ gamma,
    float* __restrict__ out)
{
    const int b  = blockIdx.x;
    const int c0 = blockIdx.y * 128;   // 2 c-tiles
    const int m0 = blockIdx.z * 128;   // 8 m-tiles

    __shared__ unsigned int sV[4096];  // V 128c x 32n: 32 A-regions
    __shared__ unsigned int sB[4096];  // attn 128m x 32n: 64 B-regions

    const int t    = threadIdx.x;
    const int lane = t & 31;
    const int w    = t >> 5;
    const int wc   = w & 1;
    const int wm   = w >> 1;

    const int sml = lane >> 2;
    const int skl = lane & 3;

    float4 acc[4][4];
    #pragma unroll
    for (int f = 0; f < 4; f++)
        #pragma unroll
        for (int g = 0; g < 4; g++) acc[f][g] = make_float4(0.f, 0.f, 0.f, 0.f);

    for (int n0 = 0; n0 < NPIX; n0 += 32) {
        // ---- stage V (A-side): 32 regions, 4 slots/thread ----
        #pragma unroll
        for (int i = 0; i < 4; i++) {
            int region = (t >> 5) + i * 8;      // c16*4 + j
            int c16 = region >> 2, j = region & 3;
            int c = c0 + c16 * 16 + sml;
            int k = n0 + j * 8 + skl;
            const float* v0 = &g_v[((size_t)b * CC + c) * NPIX + k];
            uint4 s;
            s.x = __float_as_uint(v0[0]);
            s.y = __float_as_uint(v0[4]);
            s.z = __float_as_uint(v0[8 * NPIX]);
            s.w = __float_as_uint(v0[8 * NPIX + 4]);
            ((uint4*)sV)[region * 32 + lane] = s;
        }
        // ---- stage attn (B-side): 64 regions, 8 slots/thread ----
        #pragma unroll
        for (int i = 0; i < 8; i++) {
            int region = (t >> 5) + i * 8;      // m8*4 + j
            int m8 = region >> 2, j = region & 3;
            int m = m0 + m8 * 8 + sml;
            int k = n0 + j * 8 + skl;
            const float* a0 = &g_attn[((size_t)b * NPIX + m) * NPIX + k];
            uint2 s;
            s.x = __float_as_uint(a0[0]);
            s.y = __float_as_uint(a0[4]);
            ((uint2*)sB)[region * 32 + lane] = s;
        }
        __syncthreads();

        #pragma unroll
        for (int j = 0; j < 4; j++) {
            uint4 av[4];
            #pragma unroll
            for (int f = 0; f < 4; f++)
                av[f] = ((const uint4*)sV)[((wc * 4 + f) * 4 + j) * 32 + lane];
            uint2 bv2[4];
            #pragma unroll
            for (int g = 0; g < 4; g++)
                bv2[g] = ((const uint2*)sB)[((wm * 4 + g) * 4 + j) * 32 + lane];

            #pragma unroll
            for (int f = 0; f < 4; f++)
                #pragma unroll
                for (int g = 0; g < 4; g++)
                    mma_tf32(acc[f][g], av[f].x, av[f].z, av[f].y, av[f].w,
                             bv2[g].x, bv2[g].y);
        }
        __syncthreads();
    }

    // epilogue: out = gamma * inv_s[m] * acc + x
    const float gm = *gamma;
    const int cbase = c0 + wc * 64 + (lane >> 2);
    const int mbase = m0 + wm * 32 + 2 * (lane & 3);

    #pragma unroll
    for (int f = 0; f < 4; f++) {
        #pragma unroll
        for (int g = 0; g < 4; g++) {
            const int c = cbase + f * 16;
            const int m = mbase + g * 8;
            float2 inv2 = *(const float2*)&g_inv[(size_t)b * NPIX + m];
            const float s0 = gm * inv2.x;
            const float s1 = gm * inv2.y;
            size_t a0i = ((size_t)b * CC + c) * NPIX + m;
            size_t a1i = a0i + (size_t)8 * NPIX;
            float2 x0 = *(const float2*)&x[a0i];
            float2 x1 = *(const float2*)&x[a1i];
            float2 o0, o1;
            o0.x = s0 * acc[f][g].x + x0.x;
            o0.y = s1 * acc[f][g].y + x0.y;
            o1.x = s0 * acc[f][g].z + x1.x;
            o1.y = s1 * acc[f][g].w + x1.y;
            *(float2*)&out[a0i] = o0;
            *(float2*)&out[a1i] = o1;
        }
    }
}

// ============================================================================
extern "C" void kernel_launch(void* const* d_in, const int* in_sizes, int n_in,
                              void* d_out, int out_size)
{
    (void)in_sizes; (void)n_in; (void)out_size;
    const float* x     = (const float*)d_in[0];
    const float* Wq    = (const float*)d_in[1];
    const float* bq    = (const float*)d_in[2];
    const float* Wk    = (const float*)d_in[3];
    const float* bk    = (const float*)d_in[4];
    const float* Wv    = (const float*)d_in[5];
    const float* bv    = (const float*)d_in[6];
    const float* gamma = (const float*)d_in[7];
    float* out = (float*)d_out;

    dim3 g1(BB, NROWS / 64, NPIX / 128);   // 32 x 5 x 8
    proj_kernel<<<g1, 256>>>(x, Wq, bq, Wk, bk, Wv, bv);

    dim3 g2(BB, NPIX / 64);                // 32 x 16
    energy_exp_kernel<<<g2, 256>>>();

    dim3 g4(BB, CC / 128, NPIX / 128);     // 32 x 2 x 8
    out_kernel<<<g4, 256>>>(x, gamma, out);
}

// round 13
// speedup vs baseline: 1.4801x; 1.4582x over previous
#include <cuda_runtime.h>
#include <cuda_bf16.h>
#include <math.h>

#define BB   32
#define CC   256
#define C8   32
#define NPIX 1024
#define NROWS 320   // 32 q + 32 k + 256 v rows stacked

// ---- scratch (device globals; allocation-free per harness rules) ----
__device__ float          g_q[(size_t)BB * C8 * NPIX];          // [b][d][m]  4 MB
__device__ float          g_k[(size_t)BB * C8 * NPIX];          // [b][d][n]  4 MB
__device__ __nv_bfloat16  g_v_bf[(size_t)BB * CC * NPIX];       // [b][c][n] 16 MB
__device__ __nv_bfloat16  g_attn_bf[(size_t)BB * NPIX * NPIX];  // [b][m][n] exp(E), 64 MB
__device__ float          g_inv[(size_t)BB * NPIX];             // 1/rowsum, 128 KB

// ============================================================================
// tf32 mma (verified R4/5):
//  A frag (16m x 8k) slot: lane=(m&7)*4+(k&3); uint4 =
//      (m_lo,k_lo)(m_lo,k_hi)(m_hi,k_lo)(m_hi,k_hi), consumed (x,z,y,w).
//  B frag (8n x 8k) slot: lane=(n&7)*4+(k&3); uint2 = (k_lo,k_hi).
//  D frag: row=(lane>>2)(+8), col=2*(lane&3)(+1): .x .y / .z .w
// bf16 mma m16n8k16 (PTX layout):
//  A: a0=(r,k01) a1=(r+8,k01) a2=(r,k89) a3=(r+8,k89), r=lane>>2, k0=2*(lane&3)
//  B: b0=(k01,n) b1=(k89,n), n=lane>>2
//  D identical to tf32 case.
// Staging is slot-per-thread -> lane-linear STS, zero bank conflicts.
// ============================================================================
__device__ __forceinline__ unsigned int f2tf32(float f) {
    unsigned int r;
    asm("cvt.rna.tf32.f32 %0, %1;" : "=r"(r) : "f"(f));
    return r;
}

__device__ __forceinline__ void mma_tf32(float4& d,
    unsigned int a0, unsigned int a1, unsigned int a2, unsigned int a3,
    unsigned int b0, unsigned int b1)
{
    asm volatile(
        "mma.sync.aligned.m16n8k8.row.col.f32.tf32.tf32.f32 "
        "{%0,%1,%2,%3}, {%4,%5,%6,%7}, {%8,%9}, {%0,%1,%2,%3};"
        : "+f"(d.x), "+f"(d.y), "+f"(d.z), "+f"(d.w)
        : "r"(a0), "r"(a1), "r"(a2), "r"(a3), "r"(b0), "r"(b1));
}

__device__ __forceinline__ void mma_bf16(float4& d,
    unsigned int a0, unsigned int a1, unsigned int a2, unsigned int a3,
    unsigned int b0, unsigned int b1)
{
    asm volatile(
        "mma.sync.aligned.m16n8k16.row.col.f32.bf16.bf16.f32 "
        "{%0,%1,%2,%3}, {%4,%5,%6,%7}, {%8,%9}, {%0,%1,%2,%3};"
        : "+f"(d.x), "+f"(d.y), "+f"(d.z), "+f"(d.w)
        : "r"(a0), "r"(a1), "r"(a2), "r"(a3), "r"(b0), "r"(b1));
}

// ============================================================================
// Kernel 1 (tf32 TC): fused q/k/v projection.
// P[320,1024] = W[320,256] @ X[256,1024] + bias, per batch.
// q,k stored fp32; v stored bf16.
// ============================================================================
__device__ __forceinline__ float ldW(int r, int cidx,
    const float* __restrict__ Wq, const float* __restrict__ Wk,
    const float* __restrict__ Wv)
{
    if (r < 32)      return Wq[r * CC + cidx];
    else if (r < 64) return Wk[(r - 32) * CC + cidx];
    else             return Wv[(r - 64) * CC + cidx];
}

__device__ __forceinline__ void proj_store(int b, int r, int n, float v0, float v1,
    const float* __restrict__ bq, const float* __restrict__ bk,
    const float* __restrict__ bv)
{
    if (r < 64) {
        float bias; float* dst;
        if (r < 32) { bias = bq[r];      dst = &g_q[((size_t)b * C8 + r) * NPIX]; }
        else        { bias = bk[r - 32]; dst = &g_k[((size_t)b * C8 + (r - 32)) * NPIX]; }
        float2 o; o.x = v0 + bias; o.y = v1 + bias;
        *(float2*)&dst[n] = o;
    } else {
        float bias = bv[r - 64];
        __nv_bfloat162 h = __floats2bfloat162_rn(v0 + bias, v1 + bias);
        *(__nv_bfloat162*)&g_v_bf[((size_t)b * CC + (r - 64)) * NPIX + n] = h;
    }
}

__global__ __launch_bounds__(256) void proj_kernel(
    const float* __restrict__ x,
    const float* __restrict__ Wq, const float* __restrict__ bq,
    const float* __restrict__ Wk, const float* __restrict__ bk,
    const float* __restrict__ Wv, const float* __restrict__ bv)
{
    const int b  = blockIdx.x;
    const int r0 = blockIdx.y * 64;    // 5 r-tiles
    const int n0 = blockIdx.z * 128;   // 8 n-tiles

    __shared__ unsigned int sA[2048];  // W tile 64x32: 16 A-regions x 32 x uint4
    __shared__ unsigned int sB[4096];  // X tile 128x32: 64 B-regions x 32 x uint2

    const int t    = threadIdx.x;
    const int lane = t & 31;
    const int w    = t >> 5;
    const int wm   = w & 1;
    const int wn   = w >> 1;

    const int sml = lane >> 2;
    const int skl = lane & 3;

    float4 acc[2][4];
    #pragma unroll
    for (int f = 0; f < 2; f++)
        #pragma unroll
        for (int g = 0; g < 4; g++) acc[f][g] = make_float4(0.f, 0.f, 0.f, 0.f);

    for (int c0 = 0; c0 < CC; c0 += 32) {
        #pragma unroll
        for (int i = 0; i < 2; i++) {
            int region = (t >> 5) + i * 8;      // m16*4 + j
            int m16 = region >> 2, j = region & 3;
            int r = r0 + m16 * 16 + sml;
            int k = c0 + j * 8 + skl;
            uint4 s;
            s.x = f2tf32(ldW(r,     k,     Wq, Wk, Wv));
            s.y = f2tf32(ldW(r,     k + 4, Wq, Wk, Wv));
            s.z = f2tf32(ldW(r + 8, k,     Wq, Wk, Wv));
            s.w = f2tf32(ldW(r + 8, k + 4, Wq, Wk, Wv));
            ((uint4*)sA)[region * 32 + lane] = s;
        }
        #pragma unroll
        for (int i = 0; i < 8; i++) {
            int region = (t >> 5) + i * 8;      // n8*4 + j
            int n8 = region >> 2, j = region & 3;
            int n = n0 + n8 * 8 + sml;
            int k = c0 + j * 8 + skl;
            const float* src = &x[((size_t)b * CC + k) * NPIX + n];
            uint2 s;
            s.x = f2tf32(src[0]);
            s.y = f2tf32(src[4 * NPIX]);
            ((uint2*)sB)[region * 32 + lane] = s;
        }
        __syncthreads();

        #pragma unroll
        for (int j = 0; j < 4; j++) {
            uint4 av[2];
            #pragma unroll
            for (int f = 0; f < 2; f++)
                av[f] = ((const uint4*)sA)[((wm * 2 + f) * 4 + j) * 32 + lane];
            uint2 bv2[4];
            #pragma unroll
            for (int g = 0; g < 4; g++)
                bv2[g] = ((const uint2*)sB)[((wn * 4 + g) * 4 + j) * 32 + lane];
            #pragma unroll
            for (int f = 0; f < 2; f++)
                #pragma unroll
                for (int g = 0; g < 4; g++)
                    mma_tf32(acc[f][g], av[f].x, av[f].z, av[f].y, av[f].w,
                             bv2[g].x, bv2[g].y);
        }
        __syncthreads();
    }

    const int rb = r0 + wm * 32 + (lane >> 2);
    const int nb = n0 + wn * 32 + 2 * (lane & 3);
    #pragma unroll
    for (int f = 0; f < 2; f++) {
        #pragma unroll
        for (int g = 0; g < 4; g++) {
            int r = rb + f * 16;
            int n = nb + g * 8;
            proj_store(b, r,     n, acc[f][g].x, acc[f][g].y, bq, bk, bv);
            proj_store(b, r + 8, n, acc[f][g].z, acc[f][g].w, bq, bk, bv);
        }
    }
}

// ============================================================================
// Kernel 2 (tf32 TC): fused energy + exp + row-sum.
// Writes exp(E) as bf16 to g_attn_bf, 1/rowsum (fp32) to g_inv.
// ============================================================================
__global__ __launch_bounds__(256) void energy_exp_kernel()
{
    const int b  = blockIdx.x;
    const int m0 = blockIdx.y * 64;    // 16 m-tiles

    __shared__ unsigned int sQ[2048];  // Q 64m x 32d: 16 A-regions
    __shared__ unsigned int sK[4096];  // K 128n x 32d: 64 B-regions
    __shared__ float rowsum[64];

    const int t    = threadIdx.x;
    const int lane = t & 31;
    const int w    = t >> 5;
    const int wm   = w & 1;
    const int wn   = w >> 1;

    const int sml = lane >> 2;
    const int skl = lane & 3;

    #pragma unroll
    for (int i = 0; i < 2; i++) {
        int region = (t >> 5) + i * 8;
        int m16 = region >> 2, j = region & 3;
        int m = m0 + m16 * 16 + sml;
        int d = j * 8 + skl;
        const float* q0 = &g_q[((size_t)b * C8 + d) * NPIX + m];
        uint4 s;
        s.x = f2tf32(q0[0]);
        s.y = f2tf32(q0[4 * NPIX]);
        s.z = f2tf32(q0[8]);
        s.w = f2tf32(q0[4 * NPIX + 8]);
        ((uint4*)sQ)[region * 32 + lane] = s;
    }
    if (t < 64) rowsum[t] = 0.0f;
    __syncthreads();

    for (int n0 = 0; n0 < NPIX; n0 += 128) {
        #pragma unroll
        for (int i = 0; i < 8; i++) {
            int region = (t >> 5) + i * 8;
            int n8 = region >> 2, j = region & 3;
            int n = n0 + n8 * 8 + sml;
            int d = j * 8 + skl;
            const float* k0 = &g_k[((size_t)b * C8 + d) * NPIX + n];
            uint2 s;
            s.x = f2tf32(k0[0]);
            s.y = f2tf32(k0[4 * NPIX]);
            ((uint2*)sK)[region * 32 + lane] = s;
        }
        __syncthreads();

        float4 acc[2][4];
        #pragma unroll
        for (int f = 0; f < 2; f++)
            #pragma unroll
            for (int g = 0; g < 4; g++) acc[f][g] = make_float4(0.f, 0.f, 0.f, 0.f);

        #pragma unroll
        for (int j = 0; j < 4; j++) {
            uint4 av[2];
            #pragma unroll
            for (int f = 0; f < 2; f++)
                av[f] = ((const uint4*)sQ)[((wm * 2 + f) * 4 + j) * 32 + lane];
            uint2 bv2[4];
            #pragma unroll
            for (int g = 0; g < 4; g++)
                bv2[g] = ((const uint2*)sK)[((wn * 4 + g) * 4 + j) * 32 + lane];
            #pragma unroll
            for (int f = 0; f < 2; f++)
                #pragma unroll
                for (int g = 0; g < 4; g++)
                    mma_tf32(acc[f][g], av[f].x, av[f].z, av[f].y, av[f].w,
                             bv2[g].x, bv2[g].y);
        }

        // exp, write unnormalized bf16 attn, accumulate row sums
        #pragma unroll
        for (int f = 0; f < 2; f++) {
            float slo = 0.0f, shi = 0.0f;
            const int m_lo = m0 + wm * 32 + f * 16 + (lane >> 2);
            #pragma unroll
            for (int g = 0; g < 4; g++) {
                float e0 = __expf(acc[f][g].x);
                float e1 = __expf(acc[f][g].y);
                float e2 = __expf(acc[f][g].z);
                float e3 = __expf(acc[f][g].w);
                int n = n0 + wn * 32 + g * 8 + 2 * (lane & 3);
                size_t a0 = ((size_t)b * NPIX + m_lo) * NPIX + n;
                *(__nv_bfloat162*)&g_attn_bf[a0] = __floats2bfloat162_rn(e0, e1);
                *(__nv_bfloat162*)&g_attn_bf[a0 + (size_t)8 * NPIX] = __floats2bfloat162_rn(e2, e3);
                slo += e0 + e1;
                shi += e2 + e3;
            }
            slo += __shfl_xor_sync(0xffffffffu, slo, 1);
            slo += __shfl_xor_sync(0xffffffffu, slo, 2);
            shi += __shfl_xor_sync(0xffffffffu, shi, 1);
            shi += __shfl_xor_sync(0xffffffffu, shi, 2);
            if ((lane & 3) == 0) {
                atomicAdd(&rowsum[wm * 32 + f * 16 + (lane >> 2)], slo);
                atomicAdd(&rowsum[wm * 32 + f * 16 + (lane >> 2) + 8], shi);
            }
        }
        __syncthreads();
    }

    if (t < 64)
        g_inv[(size_t)b * NPIX + m0 + t] = 1.0f / rowsum[t];
}

// ============================================================================
// Kernel 3 (bf16 TC, m16n8k16):
// out[b][c][m] = gamma * inv_s[m] * sum_n V[c][n]*expE[m][n] + x[b][c][m]
// Block tile 128(c) x 128(m), n-chunk 32 (= 2 k16 steps). smem 16 KB.
// ============================================================================
__global__ __launch_bounds__(256, 2) void out_kernel(
    const float* __restrict__ x, const float* __restrict__ gamma,
    float* __restrict__ out)
{
    const int b  = blockIdx.x;
    const int c0 = blockIdx.y * 128;   // 2 c-tiles
    const int m0 = blockIdx.z * 128;   // 8 m-tiles

    __shared__ unsigned int sV[2048];  // 16 A-regions x 32 x uint4 (8 KB)
    __shared__ unsigned int sB[2048];  // 32 B-regions x 32 x uint2 (8 KB)

    const int t    = threadIdx.x;
    const int lane = t & 31;
    const int w    = t >> 5;
    const int wc   = w & 1;
    const int wm   = w >> 1;

    const int sml  = lane >> 2;        // row within 8
    const int skl2 = 2 * (lane & 3);   // k pair base within 8

    float4 acc[4][4];
    #pragma unroll
    for (int f = 0; f < 4; f++)
        #pragma unroll
        for (int g = 0; g < 4; g++) acc[f][g] = make_float4(0.f, 0.f, 0.f, 0.f);

    for (int n0 = 0; n0 < NPIX; n0 += 32) {
        // ---- stage V (A-side): 16 regions (c16 x j), 2 slots/thread ----
        #pragma unroll
        for (int i = 0; i < 2; i++) {
            int region = (t >> 5) + i * 8;      // region = c16*2 + j
            int c16 = region >> 1, j = region & 1;
            int c = c0 + c16 * 16 + sml;
            int k = n0 + j * 16 + skl2;
            const __nv_bfloat16* v0 = &g_v_bf[((size_t)b * CC + c) * NPIX + k];
            uint4 s;
            s.x = *(const unsigned int*)(v0);                 // (c,   k..k+1)
            s.y = *(const unsigned int*)(v0 + 8 * NPIX);      // (c+8, k..k+1)
            s.z = *(const unsigned int*)(v0 + 8);             // (c,   k+8..k+9)
            s.w = *(const unsigned int*)(v0 + 8 * NPIX + 8);  // (c+8, k+8..k+9)
            ((uint4*)sV)[region * 32 + lane] = s;
        }
        // ---- stage attn (B-side): 32 regions (m8 x j), 4 slots/thread ----
        #pragma unroll
        for (int i = 0; i < 4; i++) {
            int region = (t >> 5) + i * 8;      // region = m8*2 + j
            int m8 = region >> 1, j = region & 1;
            int m = m0 + m8 * 8 + sml;
            int k = n0 + j * 16 + skl2;
            const __nv_bfloat16* a0 = &g_attn_bf[((size_t)b * NPIX + m) * NPIX + k];
            uint2 s;
            s.x = *(const unsigned int*)(a0);        // (k..k+1,   m)
            s.y = *(const unsigned int*)(a0 + 8);    // (k+8..k+9, m)
            ((uint2*)sB)[region * 32 + lane] = s;
        }
        __syncthreads();

        #pragma unroll
        for (int j = 0; j < 2; j++) {
            uint4 av[4];
            #pragma unroll
            for (int f = 0; f < 4; f++)
                av[f] = ((const uint4*)sV)[(((wc * 4 + f) << 1) + j) * 32 + lane];
            uint2 bv2[4];
            #pragma unroll
            for (int g = 0; g < 4; g++)
                bv2[g] = ((const uint2*)sB)[(((wm * 4 + g) << 1) + j) * 32 + lane];

            #pragma unroll
            for (int f = 0; f < 4; f++)
                #pragma unroll
                for (int g = 0; g < 4; g++)
                    mma_bf16(acc[f][g], av[f].x, av[f].y, av[f].z, av[f].w,
                             bv2[g].x, bv2[g].y);
        }
        __syncthreads();
    }

    // epilogue: out = gamma * inv_s[m] * acc + x
    const float gm = *gamma;
    const int cbase = c0 + wc * 64 + (lane >> 2);
    const int mbase = m0 + wm * 32 + 2 * (lane & 3);

    #pragma unroll
    for (int f = 0; f < 4; f++) {
        #pragma unroll
        for (int g = 0; g < 4; g++) {
            const int c = cbase + f * 16;
            const int m = mbase + g * 8;
            float2 inv2 = *(const float2*)&g_inv[(size_t)b * NPIX + m];
            const float s0 = gm * inv2.x;
            const float s1 = gm * inv2.y;
            size_t a0i = ((size_t)b * CC + c) * NPIX + m;
            size_t a1i = a0i + (size_t)8 * NPIX;
            float2 x0 = *(const float2*)&x[a0i];
            float2 x1 = *(const float2*)&x[a1i];
            float2 o0, o1;
            o0.x = s0 * acc[f][g].x + x0.x;
            o0.y = s1 * acc[f][g].y + x0.y;
            o1.x = s0 * acc[f][g].z + x1.x;
            o1.y = s1 * acc[f][g].w + x1.y;
            *(float2*)&out[a0i] = o0;
            *(float2*)&out[a1i] = o1;
        }
    }
}

// ============================================================================
extern "C" void kernel_launch(void* const* d_in, const int* in_sizes, int n_in,
                              void* d_out, int out_size)
{
    (void)in_sizes; (void)n_in; (void)out_size;
    const float* x     = (const float*)d_in[0];
    const float* Wq    = (const float*)d_in[1];
    const float* bq    = (const float*)d_in[2];
    const float* Wk    = (const float*)d_in[3];
    const float* bk    = (const float*)d_in[4];
    const float* Wv    = (const float*)d_in[5];
    const float* bv    = (const float*)d_in[6];
    const float* gamma = (const float*)d_in[7];
    float* out = (float*)d_out;

    dim3 g1(BB, NROWS / 64, NPIX / 128);   // 32 x 5 x 8
    proj_kernel<<<g1, 256>>>(x, Wq, bq, Wk, bk, Wv, bv);

    dim3 g2(BB, NPIX / 64);                // 32 x 16
    energy_exp_kernel<<<g2, 256>>>();

    dim3 g4(BB, CC / 128, NPIX / 128);     // 32 x 2 x 8
    out_kernel<<<g4, 256>>>(x, gamma, out);
}

// round 14
// speedup vs baseline: 1.6651x; 1.1250x over previous
#include <cuda_runtime.h>
#include <cuda_bf16.h>
#include <math.h>

#define BB   32
#define CC   256
#define C8   32
#define NPIX 1024

// ---- scratch (device globals; allocation-free per harness rules) ----
__device__ float          g_q[(size_t)BB * C8 * NPIX];          // [b][d][m]  4 MB
__device__ float          g_k[(size_t)BB * C8 * NPIX];          // [b][d][n]  4 MB
__device__ __nv_bfloat16  g_v_bf[(size_t)BB * CC * NPIX];       // [b][c][n] 16 MB
__device__ __nv_bfloat16  g_attn_bf[(size_t)BB * NPIX * NPIX];  // [b][m][n] exp(E), 64 MB
__device__ float          g_inv[(size_t)BB * NPIX];             // 1/rowsum, 128 KB

// ============================================================================
// tf32 mma (verified R4/5):
//  A frag (16m x 8k) slot: lane=(m&7)*4+(k&3); uint4 =
//      (m_lo,k_lo)(m_lo,k_hi)(m_hi,k_lo)(m_hi,k_hi), consumed (x,z,y,w).
//  B frag (8n x 8k) slot: lane=(n&7)*4+(k&3); uint2 = (k_lo,k_hi).
// bf16 mma m16n8k16 (verified R13):
//  A: a0=(r,k01) a1=(r+8,k01) a2=(r,k89) a3=(r+8,k89), r=lane>>2, k0=2*(lane&3)
//  B: b0=(k01,n) b1=(k89,n), n=lane>>2
//  D frag (both): row=(lane>>2)(+8), col=2*(lane&3)(+1): .x .y / .z .w
// Staging is slot-per-thread -> lane-linear STS, zero bank conflicts.
// ============================================================================
__device__ __forceinline__ unsigned int f2tf32(float f) {
    unsigned int r;
    asm("cvt.rna.tf32.f32 %0, %1;" : "=r"(r) : "f"(f));
    return r;
}

__device__ __forceinline__ unsigned int pkbf(float a, float b) {
    __nv_bfloat162 h = __floats2bfloat162_rn(a, b);
    return *(unsigned int*)&h;
}

__device__ __forceinline__ void mma_tf32(float4& d,
    unsigned int a0, unsigned int a1, unsigned int a2, unsigned int a3,
    unsigned int b0, unsigned int b1)
{
    asm volatile(
        "mma.sync.aligned.m16n8k8.row.col.f32.tf32.tf32.f32 "
        "{%0,%1,%2,%3}, {%4,%5,%6,%7}, {%8,%9}, {%0,%1,%2,%3};"
        : "+f"(d.x), "+f"(d.y), "+f"(d.z), "+f"(d.w)
        : "r"(a0), "r"(a1), "r"(a2), "r"(a3), "r"(b0), "r"(b1));
}

__device__ __forceinline__ void mma_bf16(float4& d,
    unsigned int a0, unsigned int a1, unsigned int a2, unsigned int a3,
    unsigned int b0, unsigned int b1)
{
    asm volatile(
        "mma.sync.aligned.m16n8k16.row.col.f32.bf16.bf16.f32 "
        "{%0,%1,%2,%3}, {%4,%5,%6,%7}, {%8,%9}, {%0,%1,%2,%3};"
        : "+f"(d.x), "+f"(d.y), "+f"(d.z), "+f"(d.w)
        : "r"(a0), "r"(a1), "r"(a2), "r"(a3), "r"(b0), "r"(b1));
}

// ============================================================================
// Kernel 1a (tf32 TC): q/k projection only (rows 0..63 of stacked [Wq;Wk]).
// Identical structure to the proven R12 proj kernel, 1 r-tile.
// ============================================================================
__device__ __forceinline__ float ldW(int r, int cidx,
    const float* __restrict__ Wq, const float* __restrict__ Wk)
{
    if (r < 32) return Wq[r * CC + cidx];
    else        return Wk[(r - 32) * CC + cidx];
}

__device__ __forceinline__ void qk_store(int b, int r, int n, float v0, float v1,
    const float* __restrict__ bq, const float* __restrict__ bk)
{
    float bias; float* dst;
    if (r < 32) { bias = bq[r];      dst = &g_q[((size_t)b * C8 + r) * NPIX]; }
    else        { bias = bk[r - 32]; dst = &g_k[((size_t)b * C8 + (r - 32)) * NPIX]; }
    float2 o; o.x = v0 + bias; o.y = v1 + bias;
    *(float2*)&dst[n] = o;
}

__global__ __launch_bounds__(256) void proj_qk_kernel(
    const float* __restrict__ x,
    const float* __restrict__ Wq, const float* __restrict__ bq,
    const float* __restrict__ Wk, const float* __restrict__ bk)
{
    const int b  = blockIdx.x;
    const int n0 = blockIdx.y * 128;   // 8 n-tiles

    __shared__ unsigned int sA[2048];  // W tile 64x32: 16 A-regions x 32 x uint4
    __shared__ unsigned int sB[4096];  // X tile 128x32: 64 B-regions x 32 x uint2

    const int t    = threadIdx.x;
    const int lane = t & 31;
    const int w    = t >> 5;
    const int wm   = w & 1;
    const int wn   = w >> 1;

    const int sml = lane >> 2;
    const int skl = lane & 3;

    float4 acc[2][4];
    #pragma unroll
    for (int f = 0; f < 2; f++)
        #pragma unroll
        for (int g = 0; g < 4; g++) acc[f][g] = make_float4(0.f, 0.f, 0.f, 0.f);

    for (int c0 = 0; c0 < CC; c0 += 32) {
        #pragma unroll
        for (int i = 0; i < 2; i++) {
            int region = (t >> 5) + i * 8;      // m16*4 + j
            int m16 = region >> 2, j = region & 3;
            int r = m16 * 16 + sml;
            int k = c0 + j * 8 + skl;
            uint4 s;
            s.x = f2tf32(ldW(r,     k,     Wq, Wk));
            s.y = f2tf32(ldW(r,     k + 4, Wq, Wk));
            s.z = f2tf32(ldW(r + 8, k,     Wq, Wk));
            s.w = f2tf32(ldW(r + 8, k + 4, Wq, Wk));
            ((uint4*)sA)[region * 32 + lane] = s;
        }
        #pragma unroll
        for (int i = 0; i < 8; i++) {
            int region = (t >> 5) + i * 8;      // n8*4 + j
            int n8 = region >> 2, j = region & 3;
            int n = n0 + n8 * 8 + sml;
            int k = c0 + j * 8 + skl;
            const float* src = &x[((size_t)b * CC + k) * NPIX + n];
            uint2 s;
            s.x = f2tf32(src[0]);
            s.y = f2tf32(src[4 * NPIX]);
            ((uint2*)sB)[region * 32 + lane] = s;
        }
        __syncthreads();

        #pragma unroll
        for (int j = 0; j < 4; j++) {
            uint4 av[2];
            #pragma unroll
            for (int f = 0; f < 2; f++)
                av[f] = ((const uint4*)sA)[((wm * 2 + f) * 4 + j) * 32 + lane];
            uint2 bv2[4];
            #pragma unroll
            for (int g = 0; g < 4; g++)
                bv2[g] = ((const uint2*)sB)[((wn * 4 + g) * 4 + j) * 32 + lane];
            #pragma unroll
            for (int f = 0; f < 2; f++)
                #pragma unroll
                for (int g = 0; g < 4; g++)
                    mma_tf32(acc[f][g], av[f].x, av[f].z, av[f].y, av[f].w,
                             bv2[g].x, bv2[g].y);
        }
        __syncthreads();
    }

    const int rb = wm * 32 + (lane >> 2);
    const int nb = n0 + wn * 32 + 2 * (lane & 3);
    #pragma unroll
    for (int f = 0; f < 2; f++) {
        #pragma unroll
        for (int g = 0; g < 4; g++) {
            int r = rb + f * 16;
            int n = nb + g * 8;
            qk_store(b, r,     n, acc[f][g].x, acc[f][g].y, bq, bk);
            qk_store(b, r + 8, n, acc[f][g].z, acc[f][g].w, bq, bk);
        }
    }
}

// ============================================================================
// Kernel 1b (bf16 TC, m16n8k16): V projection.
// V[256,1024] = Wv[256,256] @ X[256,1024] + bv, output bf16.
// Block tile 128(r) x 128(n), k-chunk 32 (2 k16 steps). out_kernel structure.
// ============================================================================
__global__ __launch_bounds__(256, 2) void proj_v_kernel(
    const float* __restrict__ x, const float* __restrict__ Wv,
    const float* __restrict__ bv)
{
    const int b  = blockIdx.x;
    const int r0 = blockIdx.y * 128;   // 2 r-tiles (Wv rows)
    const int n0 = blockIdx.z * 128;   // 8 n-tiles

    __shared__ unsigned int sA[2048];  // Wv 128r x 32k: 16 regions x 32 x uint4
    __shared__ unsigned int sX[2048];  // X 128n x 32k: 32 regions x 32 x uint2

    const int t    = threadIdx.x;
    const int lane = t & 31;
    const int w    = t >> 5;
    const int wr   = w & 1;
    const int wn   = w >> 1;

    const int sml  = lane >> 2;
    const int skl2 = 2 * (lane & 3);

    float4 acc[4][4];
    #pragma unroll
    for (int f = 0; f < 4; f++)
        #pragma unroll
        for (int g = 0; g < 4; g++) acc[f][g] = make_float4(0.f, 0.f, 0.f, 0.f);

    for (int c0 = 0; c0 < CC; c0 += 32) {
        // ---- stage Wv (A-side): 16 regions, 2 slots/thread ----
        #pragma unroll
        for (int i = 0; i < 2; i++) {
            int region = (t >> 5) + i * 8;      // r16*2 + j
            int r16 = region >> 1, j = region & 1;
            int r = r0 + r16 * 16 + sml;
            int k = c0 + j * 16 + skl2;
            const float* w0 = &Wv[r * CC + k];
            uint4 s;
            s.x = pkbf(w0[0],          w0[1]);
            s.y = pkbf(w0[8 * CC],     w0[8 * CC + 1]);
            s.z = pkbf(w0[8],          w0[9]);
            s.w = pkbf(w0[8 * CC + 8], w0[8 * CC + 9]);
            ((uint4*)sA)[region * 32 + lane] = s;
        }
        // ---- stage X (B-side): 32 regions, 4 slots/thread ----
        #pragma unroll
        for (int i = 0; i < 4; i++) {
            int region = (t >> 5) + i * 8;      // n8*2 + j
            int n8 = region >> 1, j = region & 1;
            int n = n0 + n8 * 8 + sml;
            int k = c0 + j * 16 + skl2;
            const float* xs = &x[((size_t)b * CC + k) * NPIX + n];
            uint2 s;
            s.x = pkbf(xs[0],        xs[NPIX]);
            s.y = pkbf(xs[8 * NPIX], xs[9 * NPIX]);
            ((uint2*)sX)[region * 32 + lane] = s;
        }
        __syncthreads();

        #pragma unroll
        for (int j = 0; j < 2; j++) {
            uint4 av[4];
            #pragma unroll
            for (int f = 0; f < 4; f++)
                av[f] = ((const uint4*)sA)[(((wr * 4 + f) << 1) + j) * 32 + lane];
            uint2 bx[4];
            #pragma unroll
            for (int g = 0; g < 4; g++)
                bx[g] = ((const uint2*)sX)[(((wn * 4 + g) << 1) + j) * 32 + lane];
            #pragma unroll
            for (int f = 0; f < 4; f++)
                #pragma unroll
                for (int g = 0; g < 4; g++)
                    mma_bf16(acc[f][g], av[f].x, av[f].y, av[f].z, av[f].w,
                             bx[g].x, bx[g].y);
        }
        __syncthreads();
    }

    // epilogue: + bias, store bf16
    const int rbase = r0 + wr * 64 + (lane >> 2);
    const int nbase = n0 + wn * 32 + 2 * (lane & 3);
    #pragma unroll
    for (int f = 0; f < 4; f++) {
        const int r = rbase + f * 16;
        const float b0 = bv[r];
        const float b1 = bv[r + 8];
        #pragma unroll
        for (int g = 0; g < 4; g++) {
            const int n = nbase + g * 8;
            size_t i0 = ((size_t)b * CC + r) * NPIX + n;
            *(__nv_bfloat162*)&g_v_bf[i0] =
                __floats2bfloat162_rn(acc[f][g].x + b0, acc[f][g].y + b0);
            *(__nv_bfloat162*)&g_v_bf[i0 + (size_t)8 * NPIX] =
                __floats2bfloat162_rn(acc[f][g].z + b1, acc[f][g].w + b1);
        }
    }
}

// ============================================================================
// Kernel 2 (tf32 TC): fused energy + exp + row-sum. (unchanged from R13)
// ============================================================================
__global__ __launch_bounds__(256) void energy_exp_kernel()
{
    const int b  = blockIdx.x;
    const int m0 = blockIdx.y * 64;    // 16 m-tiles

    __shared__ unsigned int sQ[2048];
    __shared__ unsigned int sK[4096];
    __shared__ float rowsum[64];

    const int t    = threadIdx.x;
    const int lane = t & 31;
    const int w    = t >> 5;
    const int wm   = w & 1;
    const int wn   = w >> 1;

    const int sml = lane >> 2;
    const int skl = lane & 3;

    #pragma unroll
    for (int i = 0; i < 2; i++) {
        int region = (t >> 5) + i * 8;
        int m16 = region >> 2, j = region & 3;
        int m = m0 + m16 * 16 + sml;
        int d = j * 8 + skl;
        const float* q0 = &g_q[((size_t)b * C8 + d) * NPIX + m];
        uint4 s;
        s.x = f2tf32(q0[0]);
        s.y = f2tf32(q0[4 * NPIX]);
        s.z = f2tf32(q0[8]);
        s.w = f2tf32(q0[4 * NPIX + 8]);
        ((uint4*)sQ)[region * 32 + lane] = s;
    }
    if (t < 64) rowsum[t] = 0.0f;
    __syncthreads();

    for (int n0 = 0; n0 < NPIX; n0 += 128) {
        #pragma unroll
        for (int i = 0; i < 8; i++) {
            int region = (t >> 5) + i * 8;
            int n8 = region >> 2, j = region & 3;
            int n = n0 + n8 * 8 + sml;
            int d = j * 8 + skl;
            const float* k0 = &g_k[((size_t)b * C8 + d) * NPIX + n];
            uint2 s;
            s.x = f2tf32(k0[0]);
            s.y = f2tf32(k0[4 * NPIX]);
            ((uint2*)sK)[region * 32 + lane] = s;
        }
        __syncthreads();

        float4 acc[2][4];
        #pragma unroll
        for (int f = 0; f < 2; f++)
            #pragma unroll
            for (int g = 0; g < 4; g++) acc[f][g] = make_float4(0.f, 0.f, 0.f, 0.f);

        #pragma unroll
        for (int j = 0; j < 4; j++) {
            uint4 av[2];
            #pragma unroll
            for (int f = 0; f < 2; f++)
                av[f] = ((const uint4*)sQ)[((wm * 2 + f) * 4 + j) * 32 + lane];
            uint2 bv2[4];
            #pragma unroll
            for (int g = 0; g < 4; g++)
                bv2[g] = ((const uint2*)sK)[((wn * 4 + g) * 4 + j) * 32 + lane];
            #pragma unroll
            for (int f = 0; f < 2; f++)
                #pragma unroll
                for (int g = 0; g < 4; g++)
                    mma_tf32(acc[f][g], av[f].x, av[f].z, av[f].y, av[f].w,
                             bv2[g].x, bv2[g].y);
        }

        #pragma unroll
        for (int f = 0; f < 2; f++) {
            float slo = 0.0f, shi = 0.0f;
            const int m_lo = m0 + wm * 32 + f * 16 + (lane >> 2);
            #pragma unroll
            for (int g = 0; g < 4; g++) {
                float e0 = __expf(acc[f][g].x);
                float e1 = __expf(acc[f][g].y);
                float e2 = __expf(acc[f][g].z);
                float e3 = __expf(acc[f][g].w);
                int n = n0 + wn * 32 + g * 8 + 2 * (lane & 3);
                size_t a0 = ((size_t)b * NPIX + m_lo) * NPIX + n;
                *(__nv_bfloat162*)&g_attn_bf[a0] = __floats2bfloat162_rn(e0, e1);
                *(__nv_bfloat162*)&g_attn_bf[a0 + (size_t)8 * NPIX] = __floats2bfloat162_rn(e2, e3);
                slo += e0 + e1;
                shi += e2 + e3;
            }
            slo += __shfl_xor_sync(0xffffffffu, slo, 1);
            slo += __shfl_xor_sync(0xffffffffu, slo, 2);
            shi += __shfl_xor_sync(0xffffffffu, shi, 1);
            shi += __shfl_xor_sync(0xffffffffu, shi, 2);
            if ((lane & 3) == 0) {
                atomicAdd(&rowsum[wm * 32 + f * 16 + (lane >> 2)], slo);
                atomicAdd(&rowsum[wm * 32 + f * 16 + (lane >> 2) + 8], shi);
            }
        }
        __syncthreads();
    }

    if (t < 64)
        g_inv[(size_t)b * NPIX + m0 + t] = 1.0f / rowsum[t];
}

// ============================================================================
// Kernel 3 (bf16 TC, m16n8k16, DOUBLE-BUFFERED):
// out[b][c][m] = gamma * inv_s[m] * sum_n V[c][n]*expE[m][n] + x[b][c][m]
// Next chunk's gmem loads held in registers, issued before current mma loop.
// ============================================================================
__global__ __launch_bounds__(256, 2) void out_kernel(
    const float* __restrict__ x, const float* __restrict__ gamma,
    float* __restrict__ out)
{
    const int b  = blockIdx.x;
    const int c0 = blockIdx.y * 128;   // 2 c-tiles
    const int m0 = blockIdx.z * 128;   // 8 m-tiles

    __shared__ unsigned int sV[2][2048];  // ping-pong A (8 KB each)
    __shared__ unsigned int sB[2][2048];  // ping-pong B (8 KB each)

    const int t    = threadIdx.x;
    const int lane = t & 31;
    const int w    = t >> 5;
    const int wc   = w & 1;
    const int wm   = w >> 1;

    const int sml  = lane >> 2;
    const int skl2 = 2 * (lane & 3);

    // per-thread staging source bases
    const __nv_bfloat16* vbase = g_v_bf + ((size_t)b * CC) * NPIX;
    const __nv_bfloat16* abase = g_attn_bf + ((size_t)b * NPIX) * NPIX;

    float4 acc[4][4];
    #pragma unroll
    for (int f = 0; f < 4; f++)
        #pragma unroll
        for (int g = 0; g < 4; g++) acc[f][g] = make_float4(0.f, 0.f, 0.f, 0.f);

    uint4 rv[2];
    uint2 ra[4];

    // ---- ldg chunk -> regs ----
    #define OUT_LDG(N0)                                                        \
        _Pragma("unroll")                                                      \
        for (int i = 0; i < 2; i++) {                                          \
            int region = (t >> 5) + i * 8;                                     \
            int c16 = region >> 1, j = region & 1;                             \
            int c = c0 + c16 * 16 + sml;                                       \
            int k = (N0) + j * 16 + skl2;                                      \
            const __nv_bfloat16* v0 = vbase + (size_t)c * NPIX + k;            \
            rv[i].x = *(const unsigned int*)(v0);                              \
            rv[i].y = *(const unsigned int*)(v0 + 8 * NPIX);                   \
            rv[i].z = *(const unsigned int*)(v0 + 8);                          \
            rv[i].w = *(const unsigned int*)(v0 + 8 * NPIX + 8);               \
        }                                                                      \
        _Pragma("unroll")                                                      \
        for (int i = 0; i < 4; i++) {                                          \
            int region = (t >> 5) + i * 8;                                     \
            int m8 = region >> 1, j = region & 1;                              \
            int m = m0 + m8 * 8 + sml;                                         \
            int k = (N0) + j * 16 + skl2;                                      \
            const __nv_bfloat16* a0 = abase + (size_t)m * NPIX + k;            \
            ra[i].x = *(const unsigned int*)(a0);                              \
            ra[i].y = *(const unsigned int*)(a0 + 8);                          \
        }

    // ---- regs -> smem buffer PB ----
    #define OUT_STS(PB)                                                        \
        _Pragma("unroll")                                                      \
        for (int i = 0; i < 2; i++)                                            \
            ((uint4*)sV[PB])[((t >> 5) + i * 8) * 32 + lane] = rv[i];          \
        _Pragma("unroll")                                                      \
        for (int i = 0; i < 4; i++)                                            \
            ((uint2*)sB[PB])[((t >> 5) + i * 8) * 32 + lane] = ra[i];

    // prologue
    OUT_LDG(0)
    OUT_STS(0)
    __syncthreads();

    int pb = 0;
    for (int n0 = 0; n0 < NPIX; n0 += 32, pb ^= 1) {
        const bool more = (n0 + 32 < NPIX);
        if (more) { OUT_LDG(n0 + 32) }

        #pragma unroll
        for (int j = 0; j < 2; j++) {
            uint4 av[4];
            #pragma unroll
            for (int f = 0; f < 4; f++)
                av[f] = ((const uint4*)sV[pb])[(((wc * 4 + f) << 1) + j) * 32 + lane];
            uint2 bv2[4];
            #pragma unroll
            for (int g = 0; g < 4; g++)
                bv2[g] = ((const uint2*)sB[pb])[(((wm * 4 + g) << 1) + j) * 32 + lane];

            #pragma unroll
            for (int f = 0; f < 4; f++)
                #pragma unroll
                for (int g = 0; g < 4; g++)
                    mma_bf16(acc[f][g], av[f].x, av[f].y, av[f].z, av[f].w,
                             bv2[g].x, bv2[g].y);
        }

        if (more) {
            OUT_STS(pb ^ 1)
            __syncthreads();
        }
    }

    // epilogue: out = gamma * inv_s[m] * acc + x
    const float gm = *gamma;
    const int cbase = c0 + wc * 64 + (lane >> 2);
    const int mbase = m0 + wm * 32 + 2 * (lane & 3);

    #pragma unroll
    for (int f = 0; f < 4; f++) {
        #pragma unroll
        for (int g = 0; g < 4; g++) {
            const int c = cbase + f * 16;
            const int m = mbase + g * 8;
            float2 inv2 = *(const float2*)&g_inv[(size_t)b * NPIX + m];
            const float s0 = gm * inv2.x;
            const float s1 = gm * inv2.y;
            size_t a0i = ((size_t)b * CC + c) * NPIX + m;
            size_t a1i = a0i + (size_t)8 * NPIX;
            float2 x0 = *(const float2*)&x[a0i];
            float2 x1 = *(const float2*)&x[a1i];
            float2 o0, o1;
            o0.x = s0 * acc[f][g].x + x0.x;
            o0.y = s1 * acc[f][g].y + x0.y;
            o1.x = s0 * acc[f][g].z + x1.x;
            o1.y = s1 * acc[f][g].w + x1.y;
            *(float2*)&out[a0i] = o0;
            *(float2*)&out[a1i] = o1;
        }
    }
}

// ============================================================================
extern "C" void kernel_launch(void* const* d_in, const int* in_sizes, int n_in,
                              void* d_out, int out_size)
{
    (void)in_sizes; (void)n_in; (void)out_size;
    const float* x     = (const float*)d_in[0];
    const float* Wq    = (const float*)d_in[1];
    const float* bq    = (const float*)d_in[2];
    const float* Wk    = (const float*)d_in[3];
    const float* bk    = (const float*)d_in[4];
    const float* Wv    = (const float*)d_in[5];
    const float* bv    = (const float*)d_in[6];
    const float* gamma = (const float*)d_in[7];
    float* out = (float*)d_out;

    dim3 g1a(BB, NPIX / 128);              // 32 x 8
    proj_qk_kernel<<<g1a, 256>>>(x, Wq, bq, Wk, bk);

    dim3 g1b(BB, CC / 128, NPIX / 128);    // 32 x 2 x 8
    proj_v_kernel<<<g1b, 256>>>(x, Wv, bv);

    dim3 g2(BB, NPIX / 64);                // 32 x 16
    energy_exp_kernel<<<g2, 256>>>();

    dim3 g4(BB, CC / 128, NPIX / 128);     // 32 x 2 x 8
    out_kernel<<<g4, 256>>>(x, gamma, out);
}